// round 1
// baseline (speedup 1.0000x reference)
#include <cuda_runtime.h>
#include <math.h>

#define NT 384
#define CZ 128
#define NH 4
#define HD 32
#define NROWS (NT*NT)   // 147456

// Scratch (device globals; no dynamic allocation allowed)
__device__ float g_znorm[(size_t)NROWS * CZ];                 // 75.5 MB
__device__ float g_qkv[(size_t)3 * NT * NH * NT * HD];        // [t][n][h][i][d], 226.5 MB
__device__ float g_gate[(size_t)NROWS * CZ];                  // 75.5 MB
__device__ float g_ao[(size_t)NROWS * CZ];                    // 75.5 MB

// ---------------------------------------------------------------------------
// Kernel 1: LayerNorm over last dim (128). One warp per row.
// ---------------------------------------------------------------------------
__global__ __launch_bounds__(256) void k_ln(const float* __restrict__ z,
                                            const float* __restrict__ lnw,
                                            const float* __restrict__ lnb) {
    const int row  = blockIdx.x * 8 + (threadIdx.x >> 5);
    const int lane = threadIdx.x & 31;
    float4 x = reinterpret_cast<const float4*>(z)[(size_t)row * 32 + lane];
    float s = x.x + x.y + x.z + x.w;
    #pragma unroll
    for (int o = 16; o > 0; o >>= 1) s += __shfl_xor_sync(0xffffffffu, s, o);
    const float mu = s * (1.0f / 128.0f);
    const float ax = x.x - mu, ay = x.y - mu, az = x.z - mu, aw = x.w - mu;
    float v = ax * ax + ay * ay + az * az + aw * aw;
    #pragma unroll
    for (int o = 16; o > 0; o >>= 1) v += __shfl_xor_sync(0xffffffffu, v, o);
    const float inv = rsqrtf(v * (1.0f / 128.0f) + 1e-5f);
    const float4 w = reinterpret_cast<const float4*>(lnw)[lane];
    const float4 b = reinterpret_cast<const float4*>(lnb)[lane];
    float4 o4;
    o4.x = ax * inv * w.x + b.x;
    o4.y = ay * inv * w.y + b.y;
    o4.z = az * inv * w.z + b.z;
    o4.w = aw * inv * w.w + b.w;
    reinterpret_cast<float4*>(g_znorm)[(size_t)row * 32 + lane] = o4;
}

// ---------------------------------------------------------------------------
// Kernel 2: SGEMM  C[147456, 512] = z_norm[147456,128] @ [qkv_w | gate_w] + bias
//   blockIdx.y in 0..3: tiles 0..2 -> qkv cols 0..383, tile 3 -> gate cols.
//   qkv written scattered into g_qkv[t][n][h][i][d]; gate -> sigmoid -> g_gate.
// BM=BN=128, BK=16, 256 threads, 8x8 micro-tiles.
// ---------------------------------------------------------------------------
__global__ __launch_bounds__(256) void k_gemm_qkvg(const float* __restrict__ qkv_w,
                                                   const float* __restrict__ qkv_b,
                                                   const float* __restrict__ gate_w,
                                                   const float* __restrict__ gate_b) {
    __shared__ float As[16][128];   // [k][m]
    __shared__ float Bs[16][128];   // [k][n]
    const int tid = threadIdx.x;
    const int tx = tid & 15, ty = tid >> 4;
    const int m0 = blockIdx.x * 128;
    const int nb = blockIdx.y;
    const int col0 = nb * 128;
    const bool isGate = (nb == 3);
    const float* W   = isGate ? gate_w : qkv_w;
    const int    wld = isGate ? 128 : 384;
    const int    wc0 = isGate ? 0   : col0;

    float acc[8][8];
    #pragma unroll
    for (int i = 0; i < 8; i++)
        #pragma unroll
        for (int j = 0; j < 8; j++) acc[i][j] = 0.0f;

    for (int k0 = 0; k0 < 128; k0 += 16) {
        #pragma unroll
        for (int t = 0; t < 2; t++) {
            const int f  = (tid << 1) + t;
            const int am = f >> 2;
            const int ak = (f & 3) << 2;
            const float4 av = *reinterpret_cast<const float4*>(
                &g_znorm[(size_t)(m0 + am) * 128 + k0 + ak]);
            As[ak + 0][am] = av.x;
            As[ak + 1][am] = av.y;
            As[ak + 2][am] = av.z;
            As[ak + 3][am] = av.w;
            const int bk = f >> 5;
            const int bn = (f & 31) << 2;
            *reinterpret_cast<float4*>(&Bs[bk][bn]) =
                *reinterpret_cast<const float4*>(&W[(size_t)(k0 + bk) * wld + wc0 + bn]);
        }
        __syncthreads();
        #pragma unroll
        for (int kk = 0; kk < 16; kk++) {
            float a[8], b[8];
            *(float4*)&a[0] = *(const float4*)&As[kk][ty * 8];
            *(float4*)&a[4] = *(const float4*)&As[kk][ty * 8 + 4];
            *(float4*)&b[0] = *(const float4*)&Bs[kk][tx * 8];
            *(float4*)&b[4] = *(const float4*)&Bs[kk][tx * 8 + 4];
            #pragma unroll
            for (int i = 0; i < 8; i++)
                #pragma unroll
                for (int j = 0; j < 8; j++)
                    acc[i][j] = fmaf(a[i], b[j], acc[i][j]);
        }
        __syncthreads();
    }

    const int cbase = col0 + tx * 8;     // global output column base (8 cols)
    if (!isGate) {
        float bias[8];
        #pragma unroll
        for (int j = 0; j < 8; j++) bias[j] = qkv_b[cbase + j];
        const int t  = cbase >> 7;       // 0..2
        const int rem = cbase & 127;
        const int h  = rem >> 5;
        const int d0 = rem & 31;         // multiple of 8, stays within one head
        #pragma unroll
        for (int i = 0; i < 8; i++) {
            const int r  = m0 + ty * 8 + i;
            const int ri = r / NT;       // q/k/v first index
            const int rn = r % NT;       // n index
            const size_t dst = (((size_t)t * NT + rn) * NH + h) * ((size_t)NT * HD)
                               + (size_t)ri * HD + d0;
            float4 v0, v1;
            v0.x = acc[i][0] + bias[0]; v0.y = acc[i][1] + bias[1];
            v0.z = acc[i][2] + bias[2]; v0.w = acc[i][3] + bias[3];
            v1.x = acc[i][4] + bias[4]; v1.y = acc[i][5] + bias[5];
            v1.z = acc[i][6] + bias[6]; v1.w = acc[i][7] + bias[7];
            *reinterpret_cast<float4*>(&g_qkv[dst])     = v0;
            *reinterpret_cast<float4*>(&g_qkv[dst + 4]) = v1;
        }
    } else {
        const int cg = cbase - 384;
        float bias[8];
        #pragma unroll
        for (int j = 0; j < 8; j++) bias[j] = gate_b[cg + j];
        #pragma unroll
        for (int i = 0; i < 8; i++) {
            const int r = m0 + ty * 8 + i;
            const size_t dst = (size_t)r * 128 + cg;
            float g[8];
            #pragma unroll
            for (int j = 0; j < 8; j++) {
                const float x = acc[i][j] + bias[j];
                g[j] = 1.0f / (1.0f + __expf(-x));
            }
            float4 v0 = make_float4(g[0], g[1], g[2], g[3]);
            float4 v1 = make_float4(g[4], g[5], g[6], g[7]);
            *reinterpret_cast<float4*>(&g_gate[dst])     = v0;
            *reinterpret_cast<float4*>(&g_gate[dst + 4]) = v1;
        }
    }
}

// ---------------------------------------------------------------------------
// Kernel 3: attention per (n,h). 384 threads, Q/K/V resident in smem.
//   S[i,j] = scale * q_i . k_j ; softmax over i (column softmax) ;
//   out[i,:] = sum_j P[i,j] v_j  with 1/l_j folded into v_j.
// ---------------------------------------------------------------------------
__global__ __launch_bounds__(384, 1) void k_attn() {
    const int n = blockIdx.x, h = blockIdx.y;
    extern __shared__ float sm[];
    float* sQ  = sm;
    float* sK  = sm + NT * HD;
    float* sV  = sm + 2 * NT * HD;
    float* sMx = sm + 3 * NT * HD;   // 384 column maxima
    const int tid = threadIdx.x;

    const size_t tstride = (size_t)NT * NH * NT * HD;
    const size_t base    = ((size_t)n * NH + h) * ((size_t)NT * HD);
    const float4* gQ = reinterpret_cast<const float4*>(g_qkv + base);
    const float4* gK = reinterpret_cast<const float4*>(g_qkv + tstride + base);
    const float4* gV = reinterpret_cast<const float4*>(g_qkv + 2 * tstride + base);
    float4* s4Q = reinterpret_cast<float4*>(sQ);
    float4* s4K = reinterpret_cast<float4*>(sK);
    float4* s4V = reinterpret_cast<float4*>(sV);
    #pragma unroll
    for (int f = tid; f < NT * HD / 4; f += 384) {
        s4Q[f] = gQ[f];
        s4K[f] = gK[f];
        s4V[f] = gV[f];
    }
    __syncthreads();

    const float scale = 0.17677669529663687f;   // 1/sqrt(32)

    // ---- pass 1: thread j owns column j; online max + sum over i ----
    {
        const int j = tid;
        float4 kf[8];
        #pragma unroll
        for (int q = 0; q < 8; q++) kf[q] = *(const float4*)(sK + j * HD + q * 4);
        float m = -1e30f, l = 0.0f;
        for (int i = 0; i < NT; i++) {
            const float* qp = sQ + i * HD;
            float s0 = 0.f, s1 = 0.f, s2 = 0.f, s3 = 0.f;
            #pragma unroll
            for (int q = 0; q < 8; q++) {
                const float4 qv = *(const float4*)(qp + q * 4);
                s0 = fmaf(qv.x, kf[q].x, s0);
                s1 = fmaf(qv.y, kf[q].y, s1);
                s2 = fmaf(qv.z, kf[q].z, s2);
                s3 = fmaf(qv.w, kf[q].w, s3);
            }
            const float s = ((s0 + s1) + (s2 + s3)) * scale;
            if (s > m) { l *= __expf(m - s); m = s; }
            l += __expf(s - m);
        }
        sMx[j] = m;
        const float inv = 1.0f / l;
        #pragma unroll
        for (int q = 0; q < 8; q++) {
            float4 v = *(float4*)(sV + j * HD + q * 4);
            v.x *= inv; v.y *= inv; v.z *= inv; v.w *= inv;
            *(float4*)(sV + j * HD + q * 4) = v;
        }
    }
    __syncthreads();

    // ---- pass 2: thread i owns output row i ----
    {
        const int i = tid;
        float4 qf[8];
        #pragma unroll
        for (int q = 0; q < 8; q++) qf[q] = *(const float4*)(sQ + i * HD + q * 4);
        float4 acc[8];
        #pragma unroll
        for (int q = 0; q < 8; q++) acc[q] = make_float4(0.f, 0.f, 0.f, 0.f);
        for (int j = 0; j < NT; j++) {
            const float* kp = sK + j * HD;
            float s0 = 0.f, s1 = 0.f, s2 = 0.f, s3 = 0.f;
            #pragma unroll
            for (int q = 0; q < 8; q++) {
                const float4 kv = *(const float4*)(kp + q * 4);
                s0 = fmaf(qf[q].x, kv.x, s0);
                s1 = fmaf(qf[q].y, kv.y, s1);
                s2 = fmaf(qf[q].z, kv.z, s2);
                s3 = fmaf(qf[q].w, kv.w, s3);
            }
            const float s = ((s0 + s1) + (s2 + s3)) * scale;
            const float e = __expf(s - sMx[j]);
            const float* vp = sV + j * HD;
            #pragma unroll
            for (int q = 0; q < 8; q++) {
                const float4 vv = *(const float4*)(vp + q * 4);
                acc[q].x = fmaf(e, vv.x, acc[q].x);
                acc[q].y = fmaf(e, vv.y, acc[q].y);
                acc[q].z = fmaf(e, vv.z, acc[q].z);
                acc[q].w = fmaf(e, vv.w, acc[q].w);
            }
        }
        float4* op = reinterpret_cast<float4*>(g_ao + ((size_t)i * NT + n) * CZ + h * HD);
        #pragma unroll
        for (int q = 0; q < 8; q++) op[q] = acc[q];
    }
}

// ---------------------------------------------------------------------------
// Kernel 4: SGEMM  tmp = g_ao @ out_w + out_b ; out = z + gate * tmp
// Same tiling as kernel 2, single 128-col tile.
// ---------------------------------------------------------------------------
__global__ __launch_bounds__(256) void k_gemm_out(const float* __restrict__ out_w,
                                                  const float* __restrict__ out_b,
                                                  const float* __restrict__ z,
                                                  float* __restrict__ out) {
    __shared__ float As[16][128];
    __shared__ float Bs[16][128];
    const int tid = threadIdx.x;
    const int tx = tid & 15, ty = tid >> 4;
    const int m0 = blockIdx.x * 128;

    float acc[8][8];
    #pragma unroll
    for (int i = 0; i < 8; i++)
        #pragma unroll
        for (int j = 0; j < 8; j++) acc[i][j] = 0.0f;

    for (int k0 = 0; k0 < 128; k0 += 16) {
        #pragma unroll
        for (int t = 0; t < 2; t++) {
            const int f  = (tid << 1) + t;
            const int am = f >> 2;
            const int ak = (f & 3) << 2;
            const float4 av = *reinterpret_cast<const float4*>(
                &g_ao[(size_t)(m0 + am) * 128 + k0 + ak]);
            As[ak + 0][am] = av.x;
            As[ak + 1][am] = av.y;
            As[ak + 2][am] = av.z;
            As[ak + 3][am] = av.w;
            const int bk = f >> 5;
            const int bn = (f & 31) << 2;
            *reinterpret_cast<float4*>(&Bs[bk][bn]) =
                *reinterpret_cast<const float4*>(&out_w[(size_t)(k0 + bk) * 128 + bn]);
        }
        __syncthreads();
        #pragma unroll
        for (int kk = 0; kk < 16; kk++) {
            float a[8], b[8];
            *(float4*)&a[0] = *(const float4*)&As[kk][ty * 8];
            *(float4*)&a[4] = *(const float4*)&As[kk][ty * 8 + 4];
            *(float4*)&b[0] = *(const float4*)&Bs[kk][tx * 8];
            *(float4*)&b[4] = *(const float4*)&Bs[kk][tx * 8 + 4];
            #pragma unroll
            for (int i = 0; i < 8; i++)
                #pragma unroll
                for (int j = 0; j < 8; j++)
                    acc[i][j] = fmaf(a[i], b[j], acc[i][j]);
        }
        __syncthreads();
    }

    float bias[8];
    #pragma unroll
    for (int j = 0; j < 8; j++) bias[j] = out_b[tx * 8 + j];
    #pragma unroll
    for (int i = 0; i < 8; i++) {
        const int r = m0 + ty * 8 + i;
        const size_t idx = (size_t)r * 128 + tx * 8;
        const float4 z0 = *reinterpret_cast<const float4*>(&z[idx]);
        const float4 z1 = *reinterpret_cast<const float4*>(&z[idx + 4]);
        const float4 g0 = *reinterpret_cast<const float4*>(&g_gate[idx]);
        const float4 g1 = *reinterpret_cast<const float4*>(&g_gate[idx + 4]);
        float4 o0, o1;
        o0.x = fmaf(g0.x, acc[i][0] + bias[0], z0.x);
        o0.y = fmaf(g0.y, acc[i][1] + bias[1], z0.y);
        o0.z = fmaf(g0.z, acc[i][2] + bias[2], z0.z);
        o0.w = fmaf(g0.w, acc[i][3] + bias[3], z0.w);
        o1.x = fmaf(g1.x, acc[i][4] + bias[4], z1.x);
        o1.y = fmaf(g1.y, acc[i][5] + bias[5], z1.y);
        o1.z = fmaf(g1.z, acc[i][6] + bias[6], z1.z);
        o1.w = fmaf(g1.w, acc[i][7] + bias[7], z1.w);
        *reinterpret_cast<float4*>(&out[idx])     = o0;
        *reinterpret_cast<float4*>(&out[idx + 4]) = o1;
    }
}

// ---------------------------------------------------------------------------
extern "C" void kernel_launch(void* const* d_in, const int* in_sizes, int n_in,
                              void* d_out, int out_size) {
    const float* z      = (const float*)d_in[0];
    const float* ln_w   = (const float*)d_in[1];
    const float* ln_b   = (const float*)d_in[2];
    const float* qkv_w  = (const float*)d_in[3];
    const float* qkv_b  = (const float*)d_in[4];
    const float* out_w  = (const float*)d_in[5];
    const float* out_b  = (const float*)d_in[6];
    const float* gate_w = (const float*)d_in[7];
    const float* gate_b = (const float*)d_in[8];
    float* out = (float*)d_out;

    const int attn_smem = (3 * NT * HD + NT) * (int)sizeof(float);   // 148992 B
    cudaFuncSetAttribute(k_attn, cudaFuncAttributeMaxDynamicSharedMemorySize, attn_smem);

    k_ln<<<NROWS / 8, 256>>>(z, ln_w, ln_b);
    k_gemm_qkvg<<<dim3(NROWS / 128, 4), 256>>>(qkv_w, qkv_b, gate_w, gate_b);
    k_attn<<<dim3(NT, NH), 384, attn_smem>>>();
    k_gemm_out<<<dim3(NROWS / 128, 1), 256>>>(out_w, out_b, z, out);
}

// round 2
// speedup vs baseline: 1.2304x; 1.2304x over previous
#include <cuda_runtime.h>
#include <math.h>

#define NT 384
#define CZ 128
#define NH 4
#define HD 32
#define NROWS (NT*NT)   // 147456

typedef unsigned long long ull;

// Scratch (device globals; no dynamic allocation allowed)
__device__ float g_znorm[(size_t)NROWS * CZ];                 // 75.5 MB
__device__ float g_qkv[(size_t)3 * NT * NH * NT * HD];        // [t][n][h][i][d], 226.5 MB
__device__ float g_gate[(size_t)NROWS * CZ];                  // 75.5 MB
__device__ float g_ao[(size_t)NROWS * CZ];                    // 75.5 MB

// ---- packed fp32x2 helpers (Blackwell FFMA2 path) -------------------------
__device__ __forceinline__ ull f2fma(ull a, ull b, ull c) {
    ull d; asm("fma.rn.f32x2 %0, %1, %2, %3;" : "=l"(d) : "l"(a), "l"(b), "l"(c));
    return d;
}
__device__ __forceinline__ ull f2pk(float lo, float hi) {
    ull r; asm("mov.b64 %0, {%1, %2};" : "=l"(r) : "f"(lo), "f"(hi));
    return r;
}
__device__ __forceinline__ float2 f2up(ull v) {
    float2 r; asm("mov.b64 {%0, %1}, %2;" : "=f"(r.x), "=f"(r.y) : "l"(v));
    return r;
}

// ---------------------------------------------------------------------------
// Kernel 1: LayerNorm over last dim (128). One warp per row.
// ---------------------------------------------------------------------------
__global__ __launch_bounds__(256) void k_ln(const float* __restrict__ z,
                                            const float* __restrict__ lnw,
                                            const float* __restrict__ lnb) {
    const int row  = blockIdx.x * 8 + (threadIdx.x >> 5);
    const int lane = threadIdx.x & 31;
    float4 x = reinterpret_cast<const float4*>(z)[(size_t)row * 32 + lane];
    float s = x.x + x.y + x.z + x.w;
    #pragma unroll
    for (int o = 16; o > 0; o >>= 1) s += __shfl_xor_sync(0xffffffffu, s, o);
    const float mu = s * (1.0f / 128.0f);
    const float ax = x.x - mu, ay = x.y - mu, az = x.z - mu, aw = x.w - mu;
    float v = ax * ax + ay * ay + az * az + aw * aw;
    #pragma unroll
    for (int o = 16; o > 0; o >>= 1) v += __shfl_xor_sync(0xffffffffu, v, o);
    const float inv = rsqrtf(v * (1.0f / 128.0f) + 1e-5f);
    const float4 w = reinterpret_cast<const float4*>(lnw)[lane];
    const float4 b = reinterpret_cast<const float4*>(lnb)[lane];
    float4 o4;
    o4.x = ax * inv * w.x + b.x;
    o4.y = ay * inv * w.y + b.y;
    o4.z = az * inv * w.z + b.z;
    o4.w = aw * inv * w.w + b.w;
    reinterpret_cast<float4*>(g_znorm)[(size_t)row * 32 + lane] = o4;
}

// ---------------------------------------------------------------------------
// Kernel 2: SGEMM  C[147456, 512] = z_norm[147456,128] @ [qkv_w | gate_w] + bias
// ---------------------------------------------------------------------------
__global__ __launch_bounds__(256) void k_gemm_qkvg(const float* __restrict__ qkv_w,
                                                   const float* __restrict__ qkv_b,
                                                   const float* __restrict__ gate_w,
                                                   const float* __restrict__ gate_b) {
    __shared__ float As[16][128];   // [k][m]
    __shared__ float Bs[16][128];   // [k][n]
    const int tid = threadIdx.x;
    const int tx = tid & 15, ty = tid >> 4;
    const int m0 = blockIdx.x * 128;
    const int nb = blockIdx.y;
    const int col0 = nb * 128;
    const bool isGate = (nb == 3);
    const float* W   = isGate ? gate_w : qkv_w;
    const int    wld = isGate ? 128 : 384;
    const int    wc0 = isGate ? 0   : col0;

    float acc[8][8];
    #pragma unroll
    for (int i = 0; i < 8; i++)
        #pragma unroll
        for (int j = 0; j < 8; j++) acc[i][j] = 0.0f;

    for (int k0 = 0; k0 < 128; k0 += 16) {
        #pragma unroll
        for (int t = 0; t < 2; t++) {
            const int f  = (tid << 1) + t;
            const int am = f >> 2;
            const int ak = (f & 3) << 2;
            const float4 av = *reinterpret_cast<const float4*>(
                &g_znorm[(size_t)(m0 + am) * 128 + k0 + ak]);
            As[ak + 0][am] = av.x;
            As[ak + 1][am] = av.y;
            As[ak + 2][am] = av.z;
            As[ak + 3][am] = av.w;
            const int bk = f >> 5;
            const int bn = (f & 31) << 2;
            *reinterpret_cast<float4*>(&Bs[bk][bn]) =
                *reinterpret_cast<const float4*>(&W[(size_t)(k0 + bk) * wld + wc0 + bn]);
        }
        __syncthreads();
        #pragma unroll
        for (int kk = 0; kk < 16; kk++) {
            float a[8], b[8];
            *(float4*)&a[0] = *(const float4*)&As[kk][ty * 8];
            *(float4*)&a[4] = *(const float4*)&As[kk][ty * 8 + 4];
            *(float4*)&b[0] = *(const float4*)&Bs[kk][tx * 8];
            *(float4*)&b[4] = *(const float4*)&Bs[kk][tx * 8 + 4];
            #pragma unroll
            for (int i = 0; i < 8; i++)
                #pragma unroll
                for (int j = 0; j < 8; j++)
                    acc[i][j] = fmaf(a[i], b[j], acc[i][j]);
        }
        __syncthreads();
    }

    const int cbase = col0 + tx * 8;
    if (!isGate) {
        float bias[8];
        #pragma unroll
        for (int j = 0; j < 8; j++) bias[j] = qkv_b[cbase + j];
        const int t  = cbase >> 7;
        const int rem = cbase & 127;
        const int h  = rem >> 5;
        const int d0 = rem & 31;
        #pragma unroll
        for (int i = 0; i < 8; i++) {
            const int r  = m0 + ty * 8 + i;
            const int ri = r / NT;
            const int rn = r % NT;
            const size_t dst = (((size_t)t * NT + rn) * NH + h) * ((size_t)NT * HD)
                               + (size_t)ri * HD + d0;
            float4 v0, v1;
            v0.x = acc[i][0] + bias[0]; v0.y = acc[i][1] + bias[1];
            v0.z = acc[i][2] + bias[2]; v0.w = acc[i][3] + bias[3];
            v1.x = acc[i][4] + bias[4]; v1.y = acc[i][5] + bias[5];
            v1.z = acc[i][6] + bias[6]; v1.w = acc[i][7] + bias[7];
            *reinterpret_cast<float4*>(&g_qkv[dst])     = v0;
            *reinterpret_cast<float4*>(&g_qkv[dst + 4]) = v1;
        }
    } else {
        const int cg = cbase - 384;
        float bias[8];
        #pragma unroll
        for (int j = 0; j < 8; j++) bias[j] = gate_b[cg + j];
        #pragma unroll
        for (int i = 0; i < 8; i++) {
            const int r = m0 + ty * 8 + i;
            const size_t dst = (size_t)r * 128 + cg;
            float g[8];
            #pragma unroll
            for (int j = 0; j < 8; j++) {
                const float x = acc[i][j] + bias[j];
                g[j] = 1.0f / (1.0f + __expf(-x));
            }
            float4 v0 = make_float4(g[0], g[1], g[2], g[3]);
            float4 v1 = make_float4(g[4], g[5], g[6], g[7]);
            *reinterpret_cast<float4*>(&g_gate[dst])     = v0;
            *reinterpret_cast<float4*>(&g_gate[dst + 4]) = v1;
        }
    }
}

// ---------------------------------------------------------------------------
// Kernel 3: attention per (n,h). 384 threads. Single-S, j-tiled, FFMA2.
//   S[i,j] = (scale*q_i) . k_j ; softmax over i (column softmax per j-tile) ;
//   1/l_j folded into V row j; out_i = sum_j e_ij * V'_j.
// ---------------------------------------------------------------------------
__global__ __launch_bounds__(384, 1) void k_attn() {
    const int n = blockIdx.x, h = blockIdx.y;
    extern __shared__ float sm[];
    float* sK   = sm;                     // [384][32]
    float* sV   = sm + NT * HD;           // [384][32]
    float* sS   = sm + 2 * NT * HD;       // [384][33] padded
    float* sRed = sS + NT * 33;           // [384]
    float* sM   = sRed + NT;              // [32]
    float* sInv = sM + 32;                // [32]
    const int tid = threadIdx.x;

    const size_t tstride = (size_t)NT * NH * NT * HD;
    const size_t base    = ((size_t)n * NH + h) * ((size_t)NT * HD);
    const float4* gK = reinterpret_cast<const float4*>(g_qkv + tstride + base);
    const float4* gV = reinterpret_cast<const float4*>(g_qkv + 2 * tstride + base);
    float4* s4K = reinterpret_cast<float4*>(sK);
    float4* s4V = reinterpret_cast<float4*>(sV);
    #pragma unroll
    for (int f = tid; f < NT * HD / 4; f += 384) {
        s4K[f] = gK[f];
        s4V[f] = gV[f];
    }

    const float scale = 0.17677669529663687f;   // 1/sqrt(32)

    // q row i=tid -> registers, pre-scaled (coalesced global read, no smem Q)
    ull qr[16];
    {
        const float4* gq = reinterpret_cast<const float4*>(g_qkv + base + (size_t)tid * HD);
        #pragma unroll
        for (int p = 0; p < 8; p++) {
            float4 v = gq[p];
            qr[2 * p]     = f2pk(v.x * scale, v.y * scale);
            qr[2 * p + 1] = f2pk(v.z * scale, v.w * scale);
        }
    }
    ull out2[16];
    #pragma unroll
    for (int p = 0; p < 16; p++) out2[p] = 0ull;

    __syncthreads();

    const int i    = tid;
    const int jcol = tid & 31;
    const int seg  = tid >> 5;
    const int ib   = seg * 32;

    for (int t = 0; t < 12; t++) {
        const int j0 = t * 32;

        // ---- phase A: S[i, j0+jj] for jj=0..31 (16 FFMA2 per dot) ----
        #pragma unroll 4
        for (int jj = 0; jj < 32; jj++) {
            const ulonglong2* kp =
                reinterpret_cast<const ulonglong2*>(sK + (j0 + jj) * HD);
            ull a0 = 0ull, a1 = 0ull;
            #pragma unroll
            for (int p = 0; p < 8; p++) {
                ulonglong2 kv = kp[p];
                a0 = f2fma(qr[2 * p],     kv.x, a0);
                a1 = f2fma(qr[2 * p + 1], kv.y, a1);
            }
            float2 u = f2up(a0), w = f2up(a1);
            sS[i * 33 + jj] = (u.x + w.x) + (u.y + w.y);
        }
        __syncthreads();

        // ---- phase B1: partial column max (12 segments x 32 cols) ----
        {
            float m = -1e30f;
            #pragma unroll
            for (int r = 0; r < 32; r++) m = fmaxf(m, sS[(ib + r) * 33 + jcol]);
            sRed[tid] = m;
        }
        __syncthreads();
        if (tid < 32) {
            float m = -1e30f;
            #pragma unroll
            for (int s = 0; s < 12; s++) m = fmaxf(m, sRed[s * 32 + tid]);
            sM[tid] = m;
        }
        __syncthreads();

        // ---- phase B2: exp in place + partial column sum ----
        {
            const float mj = sM[jcol];
            float l = 0.0f;
            #pragma unroll
            for (int r = 0; r < 32; r++) {
                const int idx = (ib + r) * 33 + jcol;
                const float e = __expf(sS[idx] - mj);
                sS[idx] = e;
                l += e;
            }
            sRed[tid] = l;
        }
        __syncthreads();
        if (tid < 32) {
            float l = 0.0f;
            #pragma unroll
            for (int s = 0; s < 12; s++) l += sRed[s * 32 + tid];
            sInv[tid] = 1.0f / l;
        }
        __syncthreads();

        // ---- phase B3: fold 1/l_j into V rows of this tile ----
        if (tid < 256) {
            const int rl = tid >> 3;
            const int c  = (tid & 7) << 2;
            const float inv = sInv[rl];
            float4* vp = reinterpret_cast<float4*>(sV + (j0 + rl) * HD + c);
            float4 v = *vp;
            v.x *= inv; v.y *= inv; v.z *= inv; v.w *= inv;
            *vp = v;
        }
        __syncthreads();

        // ---- phase C: out_i += sum_jj e_ij * V'_j ----
        #pragma unroll 2
        for (int jj = 0; jj < 32; jj++) {
            const float e = sS[i * 33 + jj];
            const ull e2 = f2pk(e, e);
            const ulonglong2* vp =
                reinterpret_cast<const ulonglong2*>(sV + (j0 + jj) * HD);
            #pragma unroll
            for (int p = 0; p < 8; p++) {
                ulonglong2 vv = vp[p];
                out2[2 * p]     = f2fma(e2, vv.x, out2[2 * p]);
                out2[2 * p + 1] = f2fma(e2, vv.y, out2[2 * p + 1]);
            }
        }
        __syncthreads();
    }

    // ---- stage to smem, then coalesced global write ----
    #pragma unroll
    for (int p = 0; p < 16; p++) {
        float2 v = f2up(out2[p]);
        sS[i * 33 + 2 * p]     = v.x;
        sS[i * 33 + 2 * p + 1] = v.y;
    }
    __syncthreads();
    for (int f = tid; f < NT * HD; f += 384) {
        const int r = f >> 5, c = f & 31;
        g_ao[((size_t)r * NT + n) * CZ + h * HD + c] = sS[r * 33 + c];
    }
}

// ---------------------------------------------------------------------------
// Kernel 4: SGEMM  tmp = g_ao @ out_w + out_b ; out = z + gate * tmp
// ---------------------------------------------------------------------------
__global__ __launch_bounds__(256) void k_gemm_out(const float* __restrict__ out_w,
                                                  const float* __restrict__ out_b,
                                                  const float* __restrict__ z,
                                                  float* __restrict__ out) {
    __shared__ float As[16][128];
    __shared__ float Bs[16][128];
    const int tid = threadIdx.x;
    const int tx = tid & 15, ty = tid >> 4;
    const int m0 = blockIdx.x * 128;

    float acc[8][8];
    #pragma unroll
    for (int i = 0; i < 8; i++)
        #pragma unroll
        for (int j = 0; j < 8; j++) acc[i][j] = 0.0f;

    for (int k0 = 0; k0 < 128; k0 += 16) {
        #pragma unroll
        for (int t = 0; t < 2; t++) {
            const int f  = (tid << 1) + t;
            const int am = f >> 2;
            const int ak = (f & 3) << 2;
            const float4 av = *reinterpret_cast<const float4*>(
                &g_ao[(size_t)(m0 + am) * 128 + k0 + ak]);
            As[ak + 0][am] = av.x;
            As[ak + 1][am] = av.y;
            As[ak + 2][am] = av.z;
            As[ak + 3][am] = av.w;
            const int bk = f >> 5;
            const int bn = (f & 31) << 2;
            *reinterpret_cast<float4*>(&Bs[bk][bn]) =
                *reinterpret_cast<const float4*>(&out_w[(size_t)(k0 + bk) * 128 + bn]);
        }
        __syncthreads();
        #pragma unroll
        for (int kk = 0; kk < 16; kk++) {
            float a[8], b[8];
            *(float4*)&a[0] = *(const float4*)&As[kk][ty * 8];
            *(float4*)&a[4] = *(const float4*)&As[kk][ty * 8 + 4];
            *(float4*)&b[0] = *(const float4*)&Bs[kk][tx * 8];
            *(float4*)&b[4] = *(const float4*)&Bs[kk][tx * 8 + 4];
            #pragma unroll
            for (int i = 0; i < 8; i++)
                #pragma unroll
                for (int j = 0; j < 8; j++)
                    acc[i][j] = fmaf(a[i], b[j], acc[i][j]);
        }
        __syncthreads();
    }

    float bias[8];
    #pragma unroll
    for (int j = 0; j < 8; j++) bias[j] = out_b[tx * 8 + j];
    #pragma unroll
    for (int i = 0; i < 8; i++) {
        const int r = m0 + ty * 8 + i;
        const size_t idx = (size_t)r * 128 + tx * 8;
        const float4 z0 = *reinterpret_cast<const float4*>(&z[idx]);
        const float4 z1 = *reinterpret_cast<const float4*>(&z[idx + 4]);
        const float4 g0 = *reinterpret_cast<const float4*>(&g_gate[idx]);
        const float4 g1 = *reinterpret_cast<const float4*>(&g_gate[idx + 4]);
        float4 o0, o1;
        o0.x = fmaf(g0.x, acc[i][0] + bias[0], z0.x);
        o0.y = fmaf(g0.y, acc[i][1] + bias[1], z0.y);
        o0.z = fmaf(g0.z, acc[i][2] + bias[2], z0.z);
        o0.w = fmaf(g0.w, acc[i][3] + bias[3], z0.w);
        o1.x = fmaf(g1.x, acc[i][4] + bias[4], z1.x);
        o1.y = fmaf(g1.y, acc[i][5] + bias[5], z1.y);
        o1.z = fmaf(g1.z, acc[i][6] + bias[6], z1.z);
        o1.w = fmaf(g1.w, acc[i][7] + bias[7], z1.w);
        *reinterpret_cast<float4*>(&out[idx])     = o0;
        *reinterpret_cast<float4*>(&out[idx + 4]) = o1;
    }
}

// ---------------------------------------------------------------------------
extern "C" void kernel_launch(void* const* d_in, const int* in_sizes, int n_in,
                              void* d_out, int out_size) {
    const float* z      = (const float*)d_in[0];
    const float* ln_w   = (const float*)d_in[1];
    const float* ln_b   = (const float*)d_in[2];
    const float* qkv_w  = (const float*)d_in[3];
    const float* qkv_b  = (const float*)d_in[4];
    const float* out_w  = (const float*)d_in[5];
    const float* out_b  = (const float*)d_in[6];
    const float* gate_w = (const float*)d_in[7];
    const float* gate_b = (const float*)d_in[8];
    float* out = (float*)d_out;

    const int attn_smem = (2 * NT * HD + NT * 33 + NT + 64) * (int)sizeof(float); // 150784 B
    cudaFuncSetAttribute(k_attn, cudaFuncAttributeMaxDynamicSharedMemorySize, attn_smem);

    k_ln<<<NROWS / 8, 256>>>(z, ln_w, ln_b);
    k_gemm_qkvg<<<dim3(NROWS / 128, 4), 256>>>(qkv_w, qkv_b, gate_w, gate_b);
    k_attn<<<dim3(NT, NH), 384, attn_smem>>>();
    k_gemm_out<<<dim3(NROWS / 128, 1), 256>>>(out_w, out_b, z, out);
}